// round 3
// baseline (speedup 1.0000x reference)
#include <cuda_runtime.h>
#include <cuda_bf16.h>
#include <cuda_fp8.h>
#include <cstdint>

#define BATCH 4096
#define NVIEW 2
#define DIM   512
#define NTOT  8192
#define NCLS  1000

#define C_EXP  20.60992915555662f   // log2(e)/0.07
#define INV_T  14.285714285714286f  // 1/0.07

// ---------------- smem layout (bytes) ----------------
#define OFF_A     0
#define A_STRIDE  528                 // 512 fp8 + 16 pad per row
#define A_BYTES   (128 * A_STRIDE)    // 67584
#define OFF_B     A_BYTES
#define B_STRIDE  272                 // 256 fp8 + 16 pad per row
#define B_STAGE   (128 * B_STRIDE)    // 34816
#define OFF_RED   (OFF_B + 3 * B_STAGE)       // 172032
#define SMEM_TOTAL (OFF_RED + 256 * 4)        // 173056

// ---------------- scratch ----------------
__device__ __align__(16) __nv_bfloat16 g_A[(size_t)NTOT * DIM];
__device__ __align__(16) uint8_t       g_A8[(size_t)NTOT * DIM];
__device__ __align__(16) float         g_Ssum[NCLS * DIM];
__device__ float g_Z[2][NTOT];
__device__ float g_loss[NTOT];
__device__ int   g_cnt[NCLS];

// ---------------- PTX helpers ----------------
__device__ __forceinline__ void cp16(uint32_t saddr, const void* g) {
    asm volatile("cp.async.cg.shared.global [%0], [%1], 16;" :: "r"(saddr), "l"(g));
}
__device__ __forceinline__ void cp_commit() { asm volatile("cp.async.commit_group;"); }
template<int N> __device__ __forceinline__ void cp_wait() {
    asm volatile("cp.async.wait_group %0;" :: "n"(N));
}
__device__ __forceinline__ void ldm4(uint32_t r[4], uint32_t addr) {
    asm volatile("ldmatrix.sync.aligned.m8n8.x4.shared.b16 {%0,%1,%2,%3}, [%4];"
        : "=r"(r[0]), "=r"(r[1]), "=r"(r[2]), "=r"(r[3]) : "r"(addr));
}
__device__ __forceinline__ void qmma(float c[4], const uint32_t a[4], const uint32_t b[2]) {
    asm volatile("mma.sync.aligned.m16n8k32.row.col.f32.e4m3.e4m3.f32 "
        "{%0,%1,%2,%3}, {%4,%5,%6,%7}, {%8,%9}, {%0,%1,%2,%3};"
        : "+f"(c[0]), "+f"(c[1]), "+f"(c[2]), "+f"(c[3])
        : "r"(a[0]), "r"(a[1]), "r"(a[2]), "r"(a[3]), "r"(b[0]), "r"(b[1]));
}
__device__ __forceinline__ uint32_t smem_u32(const void* p) {
    uint32_t a;
    asm("{ .reg .u64 t; cvta.to.shared.u64 t, %1; cvt.u32.u64 %0, t; }" : "=r"(a) : "l"(p));
    return a;
}

// ------------------------- kernel 1: normalize + view-swap -> bf16 + fp8 -------------------------
__global__ void norm_kernel(const float* __restrict__ feats) {
    int warp = threadIdx.x >> 5, lane = threadIdx.x & 31;
    int row  = blockIdx.x * 8 + warp;      // contrast-layout row
    int b = row & (BATCH - 1);
    int v = row >> 12;
    const float4* src = reinterpret_cast<const float4*>(feats + (size_t)(b * NVIEW + v) * DIM);
    float4 f[4];
    float ss = 0.f;
#pragma unroll
    for (int q = 0; q < 4; q++) {
        f[q] = src[lane + 32 * q];
        ss += f[q].x * f[q].x + f[q].y * f[q].y + f[q].z * f[q].z + f[q].w * f[q].w;
    }
#pragma unroll
    for (int o = 16; o; o >>= 1) ss += __shfl_xor_sync(0xffffffffu, ss, o);
    float sc = 1.0f / fmaxf(sqrtf(ss), 1e-8f);
    uint2* dst = reinterpret_cast<uint2*>(g_A + (size_t)row * DIM);
    uint32_t* dst8 = reinterpret_cast<uint32_t*>(g_A8 + (size_t)row * DIM);
#pragma unroll
    for (int q = 0; q < 4; q++) {
        float x = f[q].x * sc, y = f[q].y * sc, z = f[q].z * sc, w = f[q].w * sc;
        __nv_bfloat162 p0 = __floats2bfloat162_rn(x, y);
        __nv_bfloat162 p1 = __floats2bfloat162_rn(z, w);
        uint2 pk;
        pk.x = *reinterpret_cast<uint32_t*>(&p0);
        pk.y = *reinterpret_cast<uint32_t*>(&p1);
        dst[lane + 32 * q] = pk;
        __nv_fp8x2_storage_t lo = __nv_cvt_float2_to_fp8x2(make_float2(x, y), __NV_SATFINITE, __NV_E4M3);
        __nv_fp8x2_storage_t hi = __nv_cvt_float2_to_fp8x2(make_float2(z, w), __NV_SATFINITE, __NV_E4M3);
        dst8[lane + 32 * q] = (uint32_t)lo | ((uint32_t)hi << 16);
    }
}

// ------------------------- kernel 2: label histogram -------------------------
__global__ void hist_kernel(const int* __restrict__ labels) {
    __shared__ int h[NCLS];
    int t = threadIdx.x;
    for (int i = t; i < NCLS; i += 1024) h[i] = 0;
    __syncthreads();
    for (int i = t; i < BATCH; i += 1024) atomicAdd(&h[labels[i]], 1);
    __syncthreads();
    for (int i = t; i < NCLS; i += 1024) g_cnt[i] = h[i];
}

// ------------------------- kernel 3: per-class feature sums (deterministic) -------------------------
__global__ void class_sum(const int* __restrict__ labels) {
    const int cls = blockIdx.x;
    const int t = threadIdx.x, lane = t & 31;
    __shared__ int list[160];
    __shared__ int ncnt;
    if (t < 32) {
        int n = 0;
        for (int base = 0; base < BATCH; base += 32) {
            int lb = labels[base + lane];
            unsigned bal = __ballot_sync(0xffffffffu, lb == cls);
            if (lb == cls) {
                int pos = n + __popc(bal & ((1u << lane) - 1));
                if (pos < 160) list[pos] = base + lane;
            }
            n += __popc(bal);
        }
        if (lane == 0) ncnt = (n < 160) ? n : 160;
    }
    __syncthreads();
    const int n = ncnt;
    const int d = t * 4;                 // 128 threads x 4 dims
    float4 acc = make_float4(0.f, 0.f, 0.f, 0.f);
    for (int k = 0; k < n; k++) {
        int b = list[k];
#pragma unroll
        for (int v = 0; v < 2; v++) {
            const uint2 u = *reinterpret_cast<const uint2*>(g_A + (size_t)(v * BATCH + b) * DIM + d);
            float2 a0 = __bfloat1622float2(*reinterpret_cast<const __nv_bfloat162*>(&u.x));
            float2 a1 = __bfloat1622float2(*reinterpret_cast<const __nv_bfloat162*>(&u.y));
            acc.x += a0.x; acc.y += a0.y; acc.z += a1.x; acc.w += a1.y;
        }
    }
    *reinterpret_cast<float4*>(g_Ssum + cls * DIM + d) = acc;
}

// ------------------------- kernel 4: fp8 GEMM + exp-sum epilogue -------------------------
__device__ __forceinline__ void prefetch_chunk(uint32_t sbase, int t, int c, int buf, int col_base) {
    const int jt = c >> 1, ch = c & 1;
    const uint8_t* bsrc = g_A8 + (size_t)(col_base + jt * 128) * DIM + ch * 256;
#pragma unroll
    for (int s = 0; s < 8; s++) {          // 2048 16B segs / 256 threads
        int f = t + 256 * s;
        int row = f >> 4, seg = f & 15;
        cp16(sbase + OFF_B + buf * B_STAGE + row * B_STRIDE + seg * 16,
             bsrc + (size_t)row * DIM + seg * 16);
    }
}

__global__ void __launch_bounds__(256, 1) supcon_main() {
    extern __shared__ char smem[];
    const int t = threadIdx.x, lane = t & 31, wid = t >> 5;
    const int warp_m = wid >> 1, warp_n = wid & 1;
    const int row_base = blockIdx.x * 128;
    const int col_base = blockIdx.y * (NTOT / 2);
    const uint32_t sbase = smem_u32(smem);

    // full-K A tile (128 rows x 512 fp8), plain copy
    for (int f = t; f < 4096; f += 256) {
        int row = f >> 5, seg = f & 31;
        uint4 v = *reinterpret_cast<const uint4*>(g_A8 + (size_t)(row_base + row) * DIM + seg * 16);
        *reinterpret_cast<uint4*>(smem + OFF_A + row * A_STRIDE + seg * 16) = v;
    }

    const uint32_t abase = sbase + OFF_A + (warp_m * 32 + (lane & 15)) * A_STRIDE + (lane >> 4) * 16;
    const uint32_t bbase0 = sbase + OFF_B +
        (((lane & 7) + ((lane >> 4) & 1) * 8) + warp_n * 64) * B_STRIDE + ((lane >> 3) & 1) * 16;

    float acc[2][8][4];
#pragma unroll
    for (int m = 0; m < 2; m++)
#pragma unroll
        for (int n = 0; n < 8; n++)
#pragma unroll
            for (int r = 0; r < 4; r++) acc[m][n][r] = 0.f;
    float z[4] = {0.f, 0.f, 0.f, 0.f};

    const int jdiag = (row_base - col_base) >> 7;   // diagonal tile index (may be out of [0,32))

    prefetch_chunk(sbase, t, 0, 0, col_base); cp_commit();
    prefetch_chunk(sbase, t, 1, 1, col_base); cp_commit();

    const int NCHUNK = 64;
    for (int c = 0; c < NCHUNK; c++) {
        if (c < NCHUNK - 2) cp_wait<1>(); else cp_wait<0>();
        __syncthreads();                      // chunk c visible to all; buf (c+2)%3 free
        if (c + 2 < NCHUNK) { prefetch_chunk(sbase, t, c + 2, (c + 2) % 3, col_base); cp_commit(); }

        const uint32_t bb = bbase0 + (c % 3) * B_STAGE;
        const int ch = c & 1;
#pragma unroll
        for (int ks = 0; ks < 8; ks++) {
            const int koff = (ch * 8 + ks) * 32;
            uint32_t a[2][4];
            ldm4(a[0], abase + koff);
            ldm4(a[1], abase + 16 * A_STRIDE + koff);
            uint32_t b[8][2];
#pragma unroll
            for (int p = 0; p < 4; p++) {
                uint32_t r4[4];
                ldm4(r4, bb + p * (16 * B_STRIDE) + ks * 32);
                b[2 * p][0] = r4[0]; b[2 * p][1] = r4[1];
                b[2 * p + 1][0] = r4[2]; b[2 * p + 1][1] = r4[3];
            }
#pragma unroll
            for (int m = 0; m < 2; m++)
#pragma unroll
                for (int n = 0; n < 8; n++) qmma(acc[m][n], a[m], b[n]);
        }

        if (ch) {                              // tile jt = c>>1 complete -> epilogue (Z only)
            const bool dg = ((c >> 1) == jdiag);
#pragma unroll
            for (int m = 0; m < 2; m++)
#pragma unroll
                for (int n = 0; n < 8; n++)
#pragma unroll
                    for (int r = 0; r < 4; r++) {
                        const int h = r >> 1;
                        float d = acc[m][n][r];
                        float e = exp2f(d * C_EXP);
                        if (dg) {
                            int rl = warp_m * 32 + m * 16 + h * 8 + (lane >> 2);
                            int cl = warp_n * 64 + n * 8 + (lane & 3) * 2 + (r & 1);
                            if (rl == cl) e = 0.f;
                        }
                        z[m * 2 + h] += e;
                        acc[m][n][r] = 0.f;
                    }
        }
    }

    // reduce z over quad lanes, then across warp_n halves
#pragma unroll
    for (int g = 0; g < 4; g++) {
        z[g] += __shfl_xor_sync(0xffffffffu, z[g], 1);
        z[g] += __shfl_xor_sync(0xffffffffu, z[g], 2);
    }
    float* red = reinterpret_cast<float*>(smem + OFF_RED);   // [2][128]
    if ((lane & 3) == 0) {
        int g4 = lane >> 2;
#pragma unroll
        for (int m = 0; m < 2; m++)
#pragma unroll
            for (int h = 0; h < 2; h++) {
                int rl = warp_m * 32 + m * 16 + h * 8 + g4;
                red[warp_n * 128 + rl] = z[m * 2 + h];
            }
    }
    __syncthreads();
    if (t < 128) g_Z[blockIdx.y][row_base + t] = red[t] + red[128 + t];
}

// ------------------------- kernel 5: per-row loss -------------------------
__global__ void finalize1(const int* __restrict__ labels) {
    const int t = threadIdx.x, lane = t & 31, wid = t >> 5;
    const int w = blockIdx.x * 4 + wid;        // 128 blocks x 4 warps -> 512 warps, 16 rows each
    for (int rr = 0; rr < 16; rr++) {
        const int row = w * 16 + rr;
        const int b = row & (BATCH - 1);
        const int cls = labels[b];
        const uint2* arow = reinterpret_cast<const uint2*>(g_A) + (size_t)row * 128;
        const float4* srow = reinterpret_cast<const float4*>(g_Ssum) + (size_t)cls * 128;
        float dot = 0.f, self = 0.f;
#pragma unroll
        for (int q = 0; q < 4; q++) {
            uint2 u = arow[lane + 32 * q];
            float4 s = srow[lane + 32 * q];
            float2 a0 = __bfloat1622float2(*reinterpret_cast<const __nv_bfloat162*>(&u.x));
            float2 a1 = __bfloat1622float2(*reinterpret_cast<const __nv_bfloat162*>(&u.y));
            dot  += a0.x * s.x + a0.y * s.y + a1.x * s.z + a1.y * s.w;
            self += a0.x * a0.x + a0.y * a0.y + a1.x * a1.x + a1.y * a1.y;
        }
#pragma unroll
        for (int o = 16; o; o >>= 1) {
            dot  += __shfl_xor_sync(0xffffffffu, dot, o);
            self += __shfl_xor_sync(0xffffffffu, self, o);
        }
        if (lane == 0) {
            float C = 2.0f * (float)g_cnt[cls] - 1.0f;
            float Z = g_Z[0][row] + g_Z[1][row];
            float S = (dot - self) * INV_T;
            g_loss[row] = (S - C * logf(Z + 1e-8f)) / (C + 1e-8f);
        }
    }
}

// ------------------------- kernel 6: final mean -------------------------
__global__ void finalize2(float* __restrict__ out) {
    __shared__ float sr[256];
    int t = threadIdx.x;
    float a = 0.f;
    for (int r = t; r < NTOT; r += 256) a += g_loss[r];
    sr[t] = a;
    __syncthreads();
    for (int o = 128; o; o >>= 1) {
        if (t < o) sr[t] += sr[t + o];
        __syncthreads();
    }
    if (t == 0) out[0] = -sr[0] / (float)NTOT;
}

// ------------------------- launch -------------------------
extern "C" void kernel_launch(void* const* d_in, const int* in_sizes, int n_in,
                              void* d_out, int out_size) {
    const float* feats = (const float*)d_in[0];
    const int* labels = (const int*)d_in[1];
    (void)in_sizes; (void)n_in; (void)out_size;

    cudaFuncSetAttribute(supcon_main, cudaFuncAttributeMaxDynamicSharedMemorySize, SMEM_TOTAL);

    norm_kernel<<<NTOT / 8, 256>>>(feats);
    hist_kernel<<<1, 1024>>>(labels);
    class_sum<<<NCLS, 128>>>(labels);
    supcon_main<<<dim3(NTOT / 128, 2), 256, SMEM_TOTAL>>>();
    finalize1<<<128, 128>>>(labels);
    finalize2<<<1, 256>>>((float*)d_out);
}

// round 4
// speedup vs baseline: 1.4789x; 1.4789x over previous
#include <cuda_runtime.h>
#include <cuda_bf16.h>
#include <cuda_fp8.h>
#include <cstdint>

#define BATCH 4096
#define NVIEW 2
#define DIM   512
#define NTOT  8192
#define NCLS  1000

#define C_EXP  20.60992915555662f   // log2(e)/0.07
#define INV_T  14.285714285714286f  // 1/0.07

// ---------------- smem layout (bytes) ----------------
#define OFF_A      0
#define A_STRIDE   528                 // 512 fp8 + 16 pad per row
#define A_BYTES    (128 * A_STRIDE)    // 67584
#define OFF_B      A_BYTES
#define B_STRIDE   272                 // 256 fp8 + 16 pad per row
#define B_STAGE    (128 * B_STRIDE)    // 34816
#define OFF_COLRED (OFF_B + 3 * B_STAGE)      // 172032
#define OFF_RED    (OFF_COLRED + 128 * 4)     // 172544
#define SMEM_TOTAL (OFF_RED + 4 * 128 * 4)    // 174592

// ---------------- scratch ----------------
__device__ __align__(16) __nv_bfloat16 g_A[(size_t)NTOT * DIM];
__device__ __align__(16) uint8_t       g_A8[(size_t)NTOT * DIM];
__device__ __align__(16) float         g_Ssum[NCLS * DIM];
__device__ float g_Z[NTOT];
__device__ float g_loss[NTOT];
__device__ int   g_cnt[NCLS];

// ---------------- PTX helpers ----------------
__device__ __forceinline__ void cp16(uint32_t saddr, const void* g) {
    asm volatile("cp.async.cg.shared.global [%0], [%1], 16;" :: "r"(saddr), "l"(g));
}
__device__ __forceinline__ void cp_commit() { asm volatile("cp.async.commit_group;"); }
template<int N> __device__ __forceinline__ void cp_wait() {
    asm volatile("cp.async.wait_group %0;" :: "n"(N));
}
__device__ __forceinline__ void ldm4(uint32_t r[4], uint32_t addr) {
    asm volatile("ldmatrix.sync.aligned.m8n8.x4.shared.b16 {%0,%1,%2,%3}, [%4];"
        : "=r"(r[0]), "=r"(r[1]), "=r"(r[2]), "=r"(r[3]) : "r"(addr));
}
__device__ __forceinline__ void qmma(float c[4], const uint32_t a[4], const uint32_t b[2]) {
    asm volatile("mma.sync.aligned.m16n8k32.row.col.f32.e4m3.e4m3.f32 "
        "{%0,%1,%2,%3}, {%4,%5,%6,%7}, {%8,%9}, {%0,%1,%2,%3};"
        : "+f"(c[0]), "+f"(c[1]), "+f"(c[2]), "+f"(c[3])
        : "r"(a[0]), "r"(a[1]), "r"(a[2]), "r"(a[3]), "r"(b[0]), "r"(b[1]));
}
__device__ __forceinline__ uint32_t smem_u32(const void* p) {
    uint32_t a;
    asm("{ .reg .u64 t; cvta.to.shared.u64 t, %1; cvt.u32.u64 %0, t; }" : "=r"(a) : "l"(p));
    return a;
}

// ------------------------- kernel 1: normalize + view-swap -> bf16 + fp8 -------------------------
__global__ void norm_kernel(const float* __restrict__ feats) {
    int warp = threadIdx.x >> 5, lane = threadIdx.x & 31;
    int row  = blockIdx.x * 8 + warp;
    int b = row & (BATCH - 1);
    int v = row >> 12;
    const float4* src = reinterpret_cast<const float4*>(feats + (size_t)(b * NVIEW + v) * DIM);
    float4 f[4];
    float ss = 0.f;
#pragma unroll
    for (int q = 0; q < 4; q++) {
        f[q] = src[lane + 32 * q];
        ss += f[q].x * f[q].x + f[q].y * f[q].y + f[q].z * f[q].z + f[q].w * f[q].w;
    }
#pragma unroll
    for (int o = 16; o; o >>= 1) ss += __shfl_xor_sync(0xffffffffu, ss, o);
    float sc = 1.0f / fmaxf(sqrtf(ss), 1e-8f);
    uint2* dst = reinterpret_cast<uint2*>(g_A + (size_t)row * DIM);
    uint32_t* dst8 = reinterpret_cast<uint32_t*>(g_A8 + (size_t)row * DIM);
#pragma unroll
    for (int q = 0; q < 4; q++) {
        float x = f[q].x * sc, y = f[q].y * sc, z = f[q].z * sc, w = f[q].w * sc;
        __nv_bfloat162 p0 = __floats2bfloat162_rn(x, y);
        __nv_bfloat162 p1 = __floats2bfloat162_rn(z, w);
        uint2 pk;
        pk.x = *reinterpret_cast<uint32_t*>(&p0);
        pk.y = *reinterpret_cast<uint32_t*>(&p1);
        dst[lane + 32 * q] = pk;
        __nv_fp8x2_storage_t lo = __nv_cvt_float2_to_fp8x2(make_float2(x, y), __NV_SATFINITE, __NV_E4M3);
        __nv_fp8x2_storage_t hi = __nv_cvt_float2_to_fp8x2(make_float2(z, w), __NV_SATFINITE, __NV_E4M3);
        dst8[lane + 32 * q] = (uint32_t)lo | ((uint32_t)hi << 16);
    }
}

// ------------------------- kernel 2: label histogram + zero g_Z -------------------------
__global__ void hist_kernel(const int* __restrict__ labels) {
    __shared__ int h[NCLS];
    int t = threadIdx.x;
    for (int i = t; i < NCLS; i += 1024) h[i] = 0;
    for (int i = t; i < NTOT; i += 1024) g_Z[i] = 0.f;
    __syncthreads();
    for (int i = t; i < BATCH; i += 1024) atomicAdd(&h[labels[i]], 1);
    __syncthreads();
    for (int i = t; i < NCLS; i += 1024) g_cnt[i] = h[i];
}

// ------------------------- kernel 3: per-class feature sums (deterministic) -------------------------
__global__ void class_sum(const int* __restrict__ labels) {
    const int cls = blockIdx.x;
    const int t = threadIdx.x, lane = t & 31;
    __shared__ int list[160];
    __shared__ int ncnt;
    if (t < 32) {
        int n = 0;
        for (int base = 0; base < BATCH; base += 32) {
            int lb = labels[base + lane];
            unsigned bal = __ballot_sync(0xffffffffu, lb == cls);
            if (lb == cls) {
                int pos = n + __popc(bal & ((1u << lane) - 1));
                if (pos < 160) list[pos] = base + lane;
            }
            n += __popc(bal);
        }
        if (lane == 0) ncnt = (n < 160) ? n : 160;
    }
    __syncthreads();
    const int n = ncnt;
    const int d = t * 4;
    float4 acc = make_float4(0.f, 0.f, 0.f, 0.f);
    for (int k = 0; k < n; k++) {
        int b = list[k];
#pragma unroll
        for (int v = 0; v < 2; v++) {
            const uint2 u = *reinterpret_cast<const uint2*>(g_A + (size_t)(v * BATCH + b) * DIM + d);
            float2 a0 = __bfloat1622float2(*reinterpret_cast<const __nv_bfloat162*>(&u.x));
            float2 a1 = __bfloat1622float2(*reinterpret_cast<const __nv_bfloat162*>(&u.y));
            acc.x += a0.x; acc.y += a0.y; acc.z += a1.x; acc.w += a1.y;
        }
    }
    *reinterpret_cast<float4*>(g_Ssum + cls * DIM + d) = acc;
}

// ------------------------- kernel 4: fp8 GEMM on upper triangle, row+col exp-sums -------------------------
__device__ __forceinline__ void prefetch_chunk(uint32_t sbase, int t, int iblk, int cbase, int idx, int buf) {
    const int ctile = cbase + (idx >> 1), ch = idx & 1;
    const int jblk = (iblk + ctile) & 63;
    const uint8_t* bsrc = g_A8 + (size_t)(jblk * 128) * DIM + ch * 256;
#pragma unroll
    for (int s = 0; s < 4; s++) {          // 2048 16B segs / 512 threads
        int f = t + 512 * s;
        int row = f >> 4, seg = f & 15;
        cp16(sbase + OFF_B + buf * B_STAGE + row * B_STRIDE + seg * 16,
             bsrc + (size_t)row * DIM + seg * 16);
    }
}

__global__ void __launch_bounds__(512, 1) supcon_main() {
    extern __shared__ char smem[];
    const int t = threadIdx.x, lane = t & 31, wid = t >> 5;
    const int warp_m = wid >> 2, warp_n = wid & 3;      // 4 x 4 warps, 32x32 tiles
    const int iblk = blockIdx.x;                         // row block 0..63
    const int sseg = blockIdx.y;                         // c-range segment 0..1
    const int row_base = iblk * 128;
    const int cbase = sseg ? 17 : 0;
    const int cend  = sseg ? ((iblk < 32) ? 33 : 32) : 17;   // exclusive
    const int NCHUNK = 2 * (cend - cbase);
    const uint32_t sbase = smem_u32(smem);
    float* colred = reinterpret_cast<float*>(smem + OFF_COLRED);

    // full-K A tile (128 rows x 512 fp8)
    for (int f = t; f < 4096; f += 512) {
        int row = f >> 5, seg = f & 31;
        uint4 v = *reinterpret_cast<const uint4*>(g_A8 + (size_t)(row_base + row) * DIM + seg * 16);
        *reinterpret_cast<uint4*>(smem + OFF_A + row * A_STRIDE + seg * 16) = v;
    }
    if (t < 128) colred[t] = 0.f;

    const uint32_t abase = sbase + OFF_A + (warp_m * 32 + (lane & 15)) * A_STRIDE + (lane >> 4) * 16;
    const uint32_t bbase0 = sbase + OFF_B +
        (((lane & 7) + ((lane >> 4) & 1) * 8) + warp_n * 32) * B_STRIDE + ((lane >> 3) & 1) * 16;

    float acc[2][4][4];
#pragma unroll
    for (int m = 0; m < 2; m++)
#pragma unroll
        for (int n = 0; n < 4; n++)
#pragma unroll
            for (int r = 0; r < 4; r++) acc[m][n][r] = 0.f;
    float z[4] = {0.f, 0.f, 0.f, 0.f};

    prefetch_chunk(sbase, t, iblk, cbase, 0, 0); cp_commit();
    prefetch_chunk(sbase, t, iblk, cbase, 1, 1); cp_commit();

    for (int c = 0; c < NCHUNK; c++) {
        if (c < NCHUNK - 2) cp_wait<1>(); else cp_wait<0>();
        __syncthreads();
        if (c + 2 < NCHUNK) { prefetch_chunk(sbase, t, iblk, cbase, c + 2, (c + 2) % 3); cp_commit(); }

        const uint32_t bb = bbase0 + (c % 3) * B_STAGE;
        const int ch = c & 1;
#pragma unroll
        for (int ks = 0; ks < 8; ks++) {
            const int koff = (ch * 8 + ks) * 32;
            uint32_t a[2][4];
            ldm4(a[0], abase + koff);
            ldm4(a[1], abase + 16 * A_STRIDE + koff);
            uint32_t b[4][2];
#pragma unroll
            for (int p = 0; p < 2; p++) {
                uint32_t r4[4];
                ldm4(r4, bb + p * (16 * B_STRIDE) + ks * 32);
                b[2 * p][0] = r4[0]; b[2 * p][1] = r4[1];
                b[2 * p + 1][0] = r4[2]; b[2 * p + 1][1] = r4[3];
            }
#pragma unroll
            for (int m = 0; m < 2; m++)
#pragma unroll
                for (int n = 0; n < 4; n++) qmma(acc[m][n], a[m], b[n]);
        }

        if (ch) {                              // tile ctile complete
            const int ctile = cbase + (c >> 1);
            const int jblk = (iblk + ctile) & 63;
            const bool dg = (ctile == 0);
            float cs[4][2];
#pragma unroll
            for (int n = 0; n < 4; n++) { cs[n][0] = 0.f; cs[n][1] = 0.f; }
#pragma unroll
            for (int m = 0; m < 2; m++)
#pragma unroll
                for (int n = 0; n < 4; n++)
#pragma unroll
                    for (int r = 0; r < 4; r++) {
                        const int h = r >> 1;
                        float d = acc[m][n][r];
                        float e = exp2f(d * C_EXP);
                        if (dg) {
                            int rl = warp_m * 32 + m * 16 + h * 8 + (lane >> 2);
                            int cl = warp_n * 32 + n * 8 + (lane & 3) * 2 + (r & 1);
                            if (rl == cl) e = 0.f;
                        }
                        z[m * 2 + h] += e;
                        cs[n][r & 1] += e;
                        acc[m][n][r] = 0.f;
                    }
            if (!dg) {
                // reduce col partials over the 8 row-groups in this warp
#pragma unroll
                for (int n = 0; n < 4; n++)
#pragma unroll
                    for (int q = 0; q < 2; q++) {
                        float v = cs[n][q];
                        v += __shfl_xor_sync(0xffffffffu, v, 4);
                        v += __shfl_xor_sync(0xffffffffu, v, 8);
                        v += __shfl_xor_sync(0xffffffffu, v, 16);
                        cs[n][q] = v;
                    }
                if (lane < 4) {
#pragma unroll
                    for (int n = 0; n < 4; n++)
#pragma unroll
                        for (int q = 0; q < 2; q++)
                            atomicAdd(&colred[warp_n * 32 + n * 8 + lane * 2 + q], cs[n][q]);
                }
                __syncthreads();
                if (t < 128) {
                    atomicAdd(&g_Z[jblk * 128 + t], colred[t]);
                    colred[t] = 0.f;
                }
            }
        }
    }

    // row z: reduce over quad lanes, then across warp_n via smem
#pragma unroll
    for (int g = 0; g < 4; g++) {
        z[g] += __shfl_xor_sync(0xffffffffu, z[g], 1);
        z[g] += __shfl_xor_sync(0xffffffffu, z[g], 2);
    }
    float* red = reinterpret_cast<float*>(smem + OFF_RED);   // [4][128]
    __syncthreads();
    if ((lane & 3) == 0) {
        int g4 = lane >> 2;
#pragma unroll
        for (int m = 0; m < 2; m++)
#pragma unroll
            for (int h = 0; h < 2; h++) {
                int rl = warp_m * 32 + m * 16 + h * 8 + g4;
                red[warp_n * 128 + rl] = z[m * 2 + h];
            }
    }
    __syncthreads();
    if (t < 128)
        atomicAdd(&g_Z[row_base + t], red[t] + red[128 + t] + red[256 + t] + red[384 + t]);
}

// ------------------------- kernel 5: per-row loss -------------------------
__global__ void finalize1(const int* __restrict__ labels) {
    const int t = threadIdx.x, lane = t & 31, wid = t >> 5;
    const int w = blockIdx.x * 4 + wid;
    for (int rr = 0; rr < 16; rr++) {
        const int row = w * 16 + rr;
        const int b = row & (BATCH - 1);
        const int cls = labels[b];
        const uint2* arow = reinterpret_cast<const uint2*>(g_A) + (size_t)row * 128;
        const float4* srow = reinterpret_cast<const float4*>(g_Ssum) + (size_t)cls * 128;
        float dot = 0.f, self = 0.f;
#pragma unroll
        for (int q = 0; q < 4; q++) {
            uint2 u = arow[lane + 32 * q];
            float4 s = srow[lane + 32 * q];
            float2 a0 = __bfloat1622float2(*reinterpret_cast<const __nv_bfloat162*>(&u.x));
            float2 a1 = __bfloat1622float2(*reinterpret_cast<const __nv_bfloat162*>(&u.y));
            dot  += a0.x * s.x + a0.y * s.y + a1.x * s.z + a1.y * s.w;
            self += a0.x * a0.x + a0.y * a0.y + a1.x * a1.x + a1.y * a1.y;
        }
#pragma unroll
        for (int o = 16; o; o >>= 1) {
            dot  += __shfl_xor_sync(0xffffffffu, dot, o);
            self += __shfl_xor_sync(0xffffffffu, self, o);
        }
        if (lane == 0) {
            float C = 2.0f * (float)g_cnt[cls] - 1.0f;
            float Z = g_Z[row];
            float S = (dot - self) * INV_T;
            g_loss[row] = (S - C * logf(Z + 1e-8f)) / (C + 1e-8f);
        }
    }
}

// ------------------------- kernel 6: final mean -------------------------
__global__ void finalize2(float* __restrict__ out) {
    __shared__ float sr[256];
    int t = threadIdx.x;
    float a = 0.f;
    for (int r = t; r < NTOT; r += 256) a += g_loss[r];
    sr[t] = a;
    __syncthreads();
    for (int o = 128; o; o >>= 1) {
        if (t < o) sr[t] += sr[t + o];
        __syncthreads();
    }
    if (t == 0) out[0] = -sr[0] / (float)NTOT;
}

// ------------------------- launch -------------------------
extern "C" void kernel_launch(void* const* d_in, const int* in_sizes, int n_in,
                              void* d_out, int out_size) {
    const float* feats = (const float*)d_in[0];
    const int* labels = (const int*)d_in[1];
    (void)in_sizes; (void)n_in; (void)out_size;

    cudaFuncSetAttribute(supcon_main, cudaFuncAttributeMaxDynamicSharedMemorySize, SMEM_TOTAL);

    norm_kernel<<<NTOT / 8, 256>>>(feats);
    hist_kernel<<<1, 1024>>>(labels);
    class_sum<<<NCLS, 128>>>(labels);
    supcon_main<<<dim3(64, 2), 512, SMEM_TOTAL>>>();
    finalize1<<<128, 128>>>(labels);
    finalize2<<<1, 256>>>((float*)d_out);
}

// round 5
// speedup vs baseline: 1.6635x; 1.1248x over previous
#include <cuda_runtime.h>
#include <cuda_bf16.h>
#include <cuda_fp8.h>
#include <cstdint>

#define BATCH 4096
#define NVIEW 2
#define DIM   512
#define NTOT  8192
#define NCLS  1000

#define C_EXP  20.60992915555662f   // log2(e)/0.07
#define INV_T  14.285714285714286f  // 1/0.07

// ---------------- smem layout (bytes) ----------------
#define OFF_A      0
#define A_STRIDE   528                 // 512 fp8 + 16 pad per row
#define A_BYTES    (128 * A_STRIDE)    // 67584
#define OFF_B      A_BYTES
#define B_STRIDE   272                 // 256 fp8 + 16 pad per row
#define B_STAGE    (128 * B_STRIDE)    // 34816
#define OFF_RED    (OFF_B + 3 * B_STAGE)      // 172032
#define SMEM_TOTAL (OFF_RED + 4 * 128 * 4)    // 174080

// ---------------- scratch ----------------
__device__ __align__(16) __nv_bfloat16 g_A[(size_t)NTOT * DIM];
__device__ __align__(16) uint8_t       g_A8[(size_t)NTOT * DIM];
__device__ __align__(16) float         g_Ssum[NCLS * DIM];
__device__ float g_Z[NTOT];
__device__ float g_loss[NTOT];
__device__ int   g_cnt[NCLS];

// ---------------- PTX helpers ----------------
__device__ __forceinline__ void cp16(uint32_t saddr, const void* g) {
    asm volatile("cp.async.cg.shared.global [%0], [%1], 16;" :: "r"(saddr), "l"(g));
}
__device__ __forceinline__ void cp_commit() { asm volatile("cp.async.commit_group;"); }
template<int N> __device__ __forceinline__ void cp_wait() {
    asm volatile("cp.async.wait_group %0;" :: "n"(N));
}
__device__ __forceinline__ void ldm4(uint32_t r[4], uint32_t addr) {
    asm volatile("ldmatrix.sync.aligned.m8n8.x4.shared.b16 {%0,%1,%2,%3}, [%4];"
        : "=r"(r[0]), "=r"(r[1]), "=r"(r[2]), "=r"(r[3]) : "r"(addr));
}
__device__ __forceinline__ void qmma(float c[4], const uint32_t a[4], const uint32_t b[2]) {
    asm volatile("mma.sync.aligned.m16n8k32.row.col.f32.e4m3.e4m3.f32 "
        "{%0,%1,%2,%3}, {%4,%5,%6,%7}, {%8,%9}, {%0,%1,%2,%3};"
        : "+f"(c[0]), "+f"(c[1]), "+f"(c[2]), "+f"(c[3])
        : "r"(a[0]), "r"(a[1]), "r"(a[2]), "r"(a[3]), "r"(b[0]), "r"(b[1]));
}
__device__ __forceinline__ uint32_t smem_u32(const void* p) {
    uint32_t a;
    asm("{ .reg .u64 t; cvta.to.shared.u64 t, %1; cvt.u32.u64 %0, t; }" : "=r"(a) : "l"(p));
    return a;
}

// ------------------------- kernel 1: normalize + view-swap -> bf16 + fp8 -------------------------
__global__ void norm_kernel(const float* __restrict__ feats) {
    int warp = threadIdx.x >> 5, lane = threadIdx.x & 31;
    int row  = blockIdx.x * 8 + warp;
    int b = row & (BATCH - 1);
    int v = row >> 12;
    const float4* src = reinterpret_cast<const float4*>(feats + (size_t)(b * NVIEW + v) * DIM);
    float4 f[4];
    float ss = 0.f;
#pragma unroll
    for (int q = 0; q < 4; q++) {
        f[q] = src[lane + 32 * q];
        ss += f[q].x * f[q].x + f[q].y * f[q].y + f[q].z * f[q].z + f[q].w * f[q].w;
    }
#pragma unroll
    for (int o = 16; o; o >>= 1) ss += __shfl_xor_sync(0xffffffffu, ss, o);
    float sc = 1.0f / fmaxf(sqrtf(ss), 1e-8f);
    uint2* dst = reinterpret_cast<uint2*>(g_A + (size_t)row * DIM);
    uint32_t* dst8 = reinterpret_cast<uint32_t*>(g_A8 + (size_t)row * DIM);
#pragma unroll
    for (int q = 0; q < 4; q++) {
        float x = f[q].x * sc, y = f[q].y * sc, z = f[q].z * sc, w = f[q].w * sc;
        __nv_bfloat162 p0 = __floats2bfloat162_rn(x, y);
        __nv_bfloat162 p1 = __floats2bfloat162_rn(z, w);
        uint2 pk;
        pk.x = *reinterpret_cast<uint32_t*>(&p0);
        pk.y = *reinterpret_cast<uint32_t*>(&p1);
        dst[lane + 32 * q] = pk;
        __nv_fp8x2_storage_t lo = __nv_cvt_float2_to_fp8x2(make_float2(x, y), __NV_SATFINITE, __NV_E4M3);
        __nv_fp8x2_storage_t hi = __nv_cvt_float2_to_fp8x2(make_float2(z, w), __NV_SATFINITE, __NV_E4M3);
        dst8[lane + 32 * q] = (uint32_t)lo | ((uint32_t)hi << 16);
    }
}

// ------------------------- kernel 2: label histogram + zero g_Z -------------------------
__global__ void hist_kernel(const int* __restrict__ labels) {
    __shared__ int h[NCLS];
    int t = threadIdx.x;
    for (int i = t; i < NCLS; i += 1024) h[i] = 0;
    for (int i = t; i < NTOT; i += 1024) g_Z[i] = 0.f;
    __syncthreads();
    for (int i = t; i < BATCH; i += 1024) atomicAdd(&h[labels[i]], 1);
    __syncthreads();
    for (int i = t; i < NCLS; i += 1024) g_cnt[i] = h[i];
}

// ------------------------- kernel 3: per-class feature sums (deterministic) -------------------------
__global__ void class_sum(const int* __restrict__ labels) {
    const int cls = blockIdx.x;
    const int t = threadIdx.x, lane = t & 31;
    __shared__ int list[160];
    __shared__ int ncnt;
    if (t < 32) {
        int n = 0;
        for (int base = 0; base < BATCH; base += 32) {
            int lb = labels[base + lane];
            unsigned bal = __ballot_sync(0xffffffffu, lb == cls);
            if (lb == cls) {
                int pos = n + __popc(bal & ((1u << lane) - 1));
                if (pos < 160) list[pos] = base + lane;
            }
            n += __popc(bal);
        }
        if (lane == 0) ncnt = (n < 160) ? n : 160;
    }
    __syncthreads();
    const int n = ncnt;
    const int d = t * 4;
    float4 acc = make_float4(0.f, 0.f, 0.f, 0.f);
    for (int k = 0; k < n; k++) {
        int b = list[k];
#pragma unroll
        for (int v = 0; v < 2; v++) {
            const uint2 u = *reinterpret_cast<const uint2*>(g_A + (size_t)(v * BATCH + b) * DIM + d);
            float2 a0 = __bfloat1622float2(*reinterpret_cast<const __nv_bfloat162*>(&u.x));
            float2 a1 = __bfloat1622float2(*reinterpret_cast<const __nv_bfloat162*>(&u.y));
            acc.x += a0.x; acc.y += a0.y; acc.z += a1.x; acc.w += a1.y;
        }
    }
    *reinterpret_cast<float4*>(g_Ssum + cls * DIM + d) = acc;
}

// ------------------------- kernel 4: fp8 GEMM on upper triangle, row+col exp-sums -------------------------
__device__ __forceinline__ void prefetch_chunk(uint32_t sbase, int t, int iblk, int cbase, int idx, int buf) {
    const int ctile = cbase + (idx >> 1), ch = idx & 1;
    const int jblk = (iblk + ctile) & 63;
    const uint8_t* bsrc = g_A8 + (size_t)(jblk * 128) * DIM + ch * 256;
#pragma unroll
    for (int s = 0; s < 4; s++) {          // 2048 16B segs / 512 threads
        int f = t + 512 * s;
        int row = f >> 4, seg = f & 15;
        cp16(sbase + OFF_B + buf * B_STAGE + row * B_STRIDE + seg * 16,
             bsrc + (size_t)row * DIM + seg * 16);
    }
}

__global__ void __launch_bounds__(512, 1) supcon_main() {
    extern __shared__ char smem[];
    const int t = threadIdx.x, lane = t & 31, wid = t >> 5;
    const int warp_m = wid >> 2, warp_n = wid & 3;      // 4 x 4 warps, 32x32 tiles
    const int iblk = blockIdx.x;                         // row block 0..63
    const int sseg = blockIdx.y;                         // c-range segment 0..1
    const int row_base = iblk * 128;
    const int cbase = sseg ? 17 : 0;
    const int cend  = sseg ? ((iblk < 32) ? 33 : 32) : 17;   // exclusive
    const int NCHUNK = 2 * (cend - cbase);
    const uint32_t sbase = smem_u32(smem);

    // full-K A tile (128 rows x 512 fp8)
    for (int f = t; f < 4096; f += 512) {
        int row = f >> 5, seg = f & 31;
        uint4 v = *reinterpret_cast<const uint4*>(g_A8 + (size_t)(row_base + row) * DIM + seg * 16);
        *reinterpret_cast<uint4*>(smem + OFF_A + row * A_STRIDE + seg * 16) = v;
    }

    const uint32_t abase = sbase + OFF_A + (warp_m * 32 + (lane & 15)) * A_STRIDE + (lane >> 4) * 16;
    const uint32_t bbase0 = sbase + OFF_B +
        (((lane & 7) + ((lane >> 4) & 1) * 8) + warp_n * 32) * B_STRIDE + ((lane >> 3) & 1) * 16;

    float acc[2][4][4];
#pragma unroll
    for (int m = 0; m < 2; m++)
#pragma unroll
        for (int n = 0; n < 4; n++)
#pragma unroll
            for (int r = 0; r < 4; r++) acc[m][n][r] = 0.f;
    float z[4] = {0.f, 0.f, 0.f, 0.f};

    prefetch_chunk(sbase, t, iblk, cbase, 0, 0); cp_commit();
    prefetch_chunk(sbase, t, iblk, cbase, 1, 1); cp_commit();

    for (int c = 0; c < NCHUNK; c++) {
        if (c < NCHUNK - 2) cp_wait<1>(); else cp_wait<0>();
        __syncthreads();
        if (c + 2 < NCHUNK) { prefetch_chunk(sbase, t, iblk, cbase, c + 2, (c + 2) % 3); cp_commit(); }

        const uint32_t bb = bbase0 + (c % 3) * B_STAGE;
        const int ch = c & 1;
#pragma unroll
        for (int ks = 0; ks < 8; ks++) {
            const int koff = (ch * 8 + ks) * 32;
            uint32_t a[2][4];
            ldm4(a[0], abase + koff);
            ldm4(a[1], abase + 16 * A_STRIDE + koff);
            uint32_t b[4][2];
#pragma unroll
            for (int p = 0; p < 2; p++) {
                uint32_t r4[4];
                ldm4(r4, bb + p * (16 * B_STRIDE) + ks * 32);
                b[2 * p][0] = r4[0]; b[2 * p][1] = r4[1];
                b[2 * p + 1][0] = r4[2]; b[2 * p + 1][1] = r4[3];
            }
#pragma unroll
            for (int m = 0; m < 2; m++)
#pragma unroll
                for (int n = 0; n < 4; n++) qmma(acc[m][n], a[m], b[n]);
        }

        if (ch) {                              // tile ctile complete -> barrier-free epilogue
            const int ctile = cbase + (c >> 1);
            const int jblk = (iblk + ctile) & 63;
            const bool dg = (ctile == 0);
            float cs[4][2];
#pragma unroll
            for (int n = 0; n < 4; n++) { cs[n][0] = 0.f; cs[n][1] = 0.f; }
#pragma unroll
            for (int m = 0; m < 2; m++)
#pragma unroll
                for (int n = 0; n < 4; n++)
#pragma unroll
                    for (int r = 0; r < 4; r++) {
                        const int h = r >> 1;
                        float d = acc[m][n][r];
                        float e = exp2f(d * C_EXP);
                        if (dg) {
                            int rl = warp_m * 32 + m * 16 + h * 8 + (lane >> 2);
                            int cl = warp_n * 32 + n * 8 + (lane & 3) * 2 + (r & 1);
                            if (rl == cl) e = 0.f;
                        }
                        z[m * 2 + h] += e;
                        cs[n][r & 1] += e;
                        acc[m][n][r] = 0.f;
                    }
            if (!dg) {
                // reduce col partials over the 8 row-groups in this warp, then REDG direct
#pragma unroll
                for (int n = 0; n < 4; n++)
#pragma unroll
                    for (int q = 0; q < 2; q++) {
                        float v = cs[n][q];
                        v += __shfl_xor_sync(0xffffffffu, v, 4);
                        v += __shfl_xor_sync(0xffffffffu, v, 8);
                        v += __shfl_xor_sync(0xffffffffu, v, 16);
                        cs[n][q] = v;
                    }
                if (lane < 4) {
                    float* zj = &g_Z[jblk * 128 + warp_n * 32 + lane * 2];
#pragma unroll
                    for (int n = 0; n < 4; n++) {
                        atomicAdd(&zj[n * 8 + 0], cs[n][0]);
                        atomicAdd(&zj[n * 8 + 1], cs[n][1]);
                    }
                }
            }
        }
    }

    // row z: reduce over quad lanes, then across warp_n via smem
#pragma unroll
    for (int g = 0; g < 4; g++) {
        z[g] += __shfl_xor_sync(0xffffffffu, z[g], 1);
        z[g] += __shfl_xor_sync(0xffffffffu, z[g], 2);
    }
    float* red = reinterpret_cast<float*>(smem + OFF_RED);   // [4][128]
    __syncthreads();
    if ((lane & 3) == 0) {
        int g4 = lane >> 2;
#pragma unroll
        for (int m = 0; m < 2; m++)
#pragma unroll
            for (int h = 0; h < 2; h++) {
                int rl = warp_m * 32 + m * 16 + h * 8 + g4;
                red[warp_n * 128 + rl] = z[m * 2 + h];
            }
    }
    __syncthreads();
    if (t < 128)
        atomicAdd(&g_Z[row_base + t], red[t] + red[128 + t] + red[256 + t] + red[384 + t]);
}

// ------------------------- kernel 5: per-row loss (one warp per row) -------------------------
__global__ void finalize1(const int* __restrict__ labels) {
    const int t = threadIdx.x, lane = t & 31, wid = t >> 5;
    const int row = blockIdx.x * 8 + wid;
    const int b = row & (BATCH - 1);
    const int cls = labels[b];
    const uint2* arow = reinterpret_cast<const uint2*>(g_A) + (size_t)row * 128;
    const float4* srow = reinterpret_cast<const float4*>(g_Ssum) + (size_t)cls * 128;
    float dot = 0.f, self = 0.f;
#pragma unroll
    for (int q = 0; q < 4; q++) {
        uint2 u = arow[lane + 32 * q];
        float4 s = srow[lane + 32 * q];
        float2 a0 = __bfloat1622float2(*reinterpret_cast<const __nv_bfloat162*>(&u.x));
        float2 a1 = __bfloat1622float2(*reinterpret_cast<const __nv_bfloat162*>(&u.y));
        dot  += a0.x * s.x + a0.y * s.y + a1.x * s.z + a1.y * s.w;
        self += a0.x * a0.x + a0.y * a0.y + a1.x * a1.x + a1.y * a1.y;
    }
#pragma unroll
    for (int o = 16; o; o >>= 1) {
        dot  += __shfl_xor_sync(0xffffffffu, dot, o);
        self += __shfl_xor_sync(0xffffffffu, self, o);
    }
    if (lane == 0) {
        float C = 2.0f * (float)g_cnt[cls] - 1.0f;
        float Z = g_Z[row];
        float S = (dot - self) * INV_T;
        g_loss[row] = (S - C * logf(Z + 1e-8f)) / (C + 1e-8f);
    }
}

// ------------------------- kernel 6: final mean -------------------------
__global__ void finalize2(float* __restrict__ out) {
    __shared__ float sr[256];
    int t = threadIdx.x;
    float a = 0.f;
    for (int r = t; r < NTOT; r += 256) a += g_loss[r];
    sr[t] = a;
    __syncthreads();
    for (int o = 128; o; o >>= 1) {
        if (t < o) sr[t] += sr[t + o];
        __syncthreads();
    }
    if (t == 0) out[0] = -sr[0] / (float)NTOT;
}

// ------------------------- launch -------------------------
extern "C" void kernel_launch(void* const* d_in, const int* in_sizes, int n_in,
                              void* d_out, int out_size) {
    const float* feats = (const float*)d_in[0];
    const int* labels = (const int*)d_in[1];
    (void)in_sizes; (void)n_in; (void)out_size;

    cudaFuncSetAttribute(supcon_main, cudaFuncAttributeMaxDynamicSharedMemorySize, SMEM_TOTAL);

    norm_kernel<<<NTOT / 8, 256>>>(feats);
    hist_kernel<<<1, 1024>>>(labels);
    class_sum<<<NCLS, 128>>>(labels);
    supcon_main<<<dim3(64, 2), 512, SMEM_TOTAL>>>();
    finalize1<<<NTOT / 8, 256>>>(labels);
    finalize2<<<1, 256>>>((float*)d_out);
}

// round 6
// speedup vs baseline: 1.6702x; 1.0040x over previous
#include <cuda_runtime.h>
#include <cuda_bf16.h>
#include <cuda_fp8.h>
#include <cstdint>

#define BATCH 4096
#define NVIEW 2
#define DIM   512
#define NTOT  8192
#define NCLS  1000

#define C_EXP  20.60992915555662f   // log2(e)/0.07
#define INV_T  14.285714285714286f  // 1/0.07
#define EBIAS  10.0f                // exp2 bias for fp16 range
#define ESCALE 1024.0f              // 2^EBIAS

// ---------------- smem layout (bytes) ----------------
#define OFF_A      0
#define A_STRIDE   528                 // 512 fp8 + 16 pad per row
#define A_BYTES    (128 * A_STRIDE)    // 67584
#define OFF_B      A_BYTES
#define B_STRIDE   272                 // 256 fp8 + 16 pad per row
#define B_STAGE    (128 * B_STRIDE)    // 34816
#define OFF_RED    (OFF_B + 3 * B_STAGE)      // 172032
#define SMEM_TOTAL (OFF_RED + 4 * 128 * 4)    // 174080

// ---------------- scratch ----------------
__device__ __align__(16) __nv_bfloat16 g_A[(size_t)NTOT * DIM];
__device__ __align__(16) uint8_t       g_A8[(size_t)NTOT * DIM];
__device__ __align__(16) float         g_Ssum[NCLS * DIM];
__device__ float g_Z[NTOT];
__device__ float g_loss[NTOT];
__device__ int   g_cnt[NCLS];

// ---------------- PTX helpers ----------------
__device__ __forceinline__ void cp16(uint32_t saddr, const void* g) {
    asm volatile("cp.async.cg.shared.global [%0], [%1], 16;" :: "r"(saddr), "l"(g));
}
__device__ __forceinline__ void cp_commit() { asm volatile("cp.async.commit_group;"); }
template<int N> __device__ __forceinline__ void cp_wait() {
    asm volatile("cp.async.wait_group %0;" :: "n"(N));
}
__device__ __forceinline__ void ldm4(uint32_t r[4], uint32_t addr) {
    asm volatile("ldmatrix.sync.aligned.m8n8.x4.shared.b16 {%0,%1,%2,%3}, [%4];"
        : "=r"(r[0]), "=r"(r[1]), "=r"(r[2]), "=r"(r[3]) : "r"(addr));
}
__device__ __forceinline__ void qmma(float c[4], const uint32_t a[4], const uint32_t b[2]) {
    asm volatile("mma.sync.aligned.m16n8k32.row.col.f32.e4m3.e4m3.f32 "
        "{%0,%1,%2,%3}, {%4,%5,%6,%7}, {%8,%9}, {%0,%1,%2,%3};"
        : "+f"(c[0]), "+f"(c[1]), "+f"(c[2]), "+f"(c[3])
        : "r"(a[0]), "r"(a[1]), "r"(a[2]), "r"(a[3]), "r"(b[0]), "r"(b[1]));
}
__device__ __forceinline__ uint32_t smem_u32(const void* p) {
    uint32_t a;
    asm("{ .reg .u64 t; cvta.to.shared.u64 t, %1; cvt.u32.u64 %0, t; }" : "=r"(a) : "l"(p));
    return a;
}
__device__ __forceinline__ uint32_t pack_h2(float lo, float hi) {
    uint32_t h;
    asm("cvt.rn.f16x2.f32 %0, %1, %2;" : "=r"(h) : "f"(hi), "f"(lo));
    return h;
}
__device__ __forceinline__ uint32_t ex2_h2(uint32_t x) {
    uint32_t e;
    asm("ex2.approx.f16x2 %0, %1;" : "=r"(e) : "r"(x));
    return e;
}
__device__ __forceinline__ uint32_t hadd2(uint32_t a, uint32_t b) {
    uint32_t d;
    asm("add.rn.f16x2 %0, %1, %2;" : "=r"(d) : "r"(a), "r"(b));
    return d;
}
__device__ __forceinline__ float2 h2_to_f2(uint32_t h) {
    float lo, hi;
    asm("{ .reg .f16 l, hh; mov.b32 {l, hh}, %2; cvt.f32.f16 %0, l; cvt.f32.f16 %1, hh; }"
        : "=f"(lo), "=f"(hi) : "r"(h));
    return make_float2(lo, hi);
}

// ------------------------- kernel 1: normalize + view-swap -> bf16 + fp8 -------------------------
__global__ void norm_kernel(const float* __restrict__ feats) {
    int warp = threadIdx.x >> 5, lane = threadIdx.x & 31;
    int row  = blockIdx.x * 8 + warp;
    int b = row & (BATCH - 1);
    int v = row >> 12;
    const float4* src = reinterpret_cast<const float4*>(feats + (size_t)(b * NVIEW + v) * DIM);
    float4 f[4];
    float ss = 0.f;
#pragma unroll
    for (int q = 0; q < 4; q++) {
        f[q] = src[lane + 32 * q];
        ss += f[q].x * f[q].x + f[q].y * f[q].y + f[q].z * f[q].z + f[q].w * f[q].w;
    }
#pragma unroll
    for (int o = 16; o; o >>= 1) ss += __shfl_xor_sync(0xffffffffu, ss, o);
    float sc = 1.0f / fmaxf(sqrtf(ss), 1e-8f);
    uint2* dst = reinterpret_cast<uint2*>(g_A + (size_t)row * DIM);
    uint32_t* dst8 = reinterpret_cast<uint32_t*>(g_A8 + (size_t)row * DIM);
#pragma unroll
    for (int q = 0; q < 4; q++) {
        float x = f[q].x * sc, y = f[q].y * sc, z = f[q].z * sc, w = f[q].w * sc;
        __nv_bfloat162 p0 = __floats2bfloat162_rn(x, y);
        __nv_bfloat162 p1 = __floats2bfloat162_rn(z, w);
        uint2 pk;
        pk.x = *reinterpret_cast<uint32_t*>(&p0);
        pk.y = *reinterpret_cast<uint32_t*>(&p1);
        dst[lane + 32 * q] = pk;
        __nv_fp8x2_storage_t lo = __nv_cvt_float2_to_fp8x2(make_float2(x, y), __NV_SATFINITE, __NV_E4M3);
        __nv_fp8x2_storage_t hi = __nv_cvt_float2_to_fp8x2(make_float2(z, w), __NV_SATFINITE, __NV_E4M3);
        dst8[lane + 32 * q] = (uint32_t)lo | ((uint32_t)hi << 16);
    }
}

// ------------------------- kernel 2: label histogram + zero g_Z -------------------------
__global__ void hist_kernel(const int* __restrict__ labels) {
    __shared__ int h[NCLS];
    int t = threadIdx.x;
    for (int i = t; i < NCLS; i += 1024) h[i] = 0;
    for (int i = t; i < NTOT; i += 1024) g_Z[i] = 0.f;
    __syncthreads();
    for (int i = t; i < BATCH; i += 1024) atomicAdd(&h[labels[i]], 1);
    __syncthreads();
    for (int i = t; i < NCLS; i += 1024) g_cnt[i] = h[i];
}

// ------------------------- kernel 3: per-class feature sums (deterministic) -------------------------
__global__ void class_sum(const int* __restrict__ labels) {
    const int cls = blockIdx.x;
    const int t = threadIdx.x, lane = t & 31;
    __shared__ int list[160];
    __shared__ int ncnt;
    if (t < 32) {
        int n = 0;
        for (int base = 0; base < BATCH; base += 32) {
            int lb = labels[base + lane];
            unsigned bal = __ballot_sync(0xffffffffu, lb == cls);
            if (lb == cls) {
                int pos = n + __popc(bal & ((1u << lane) - 1));
                if (pos < 160) list[pos] = base + lane;
            }
            n += __popc(bal);
        }
        if (lane == 0) ncnt = (n < 160) ? n : 160;
    }
    __syncthreads();
    const int n = ncnt;
    const int d = t * 4;
    float4 acc = make_float4(0.f, 0.f, 0.f, 0.f);
    for (int k = 0; k < n; k++) {
        int b = list[k];
#pragma unroll
        for (int v = 0; v < 2; v++) {
            const uint2 u = *reinterpret_cast<const uint2*>(g_A + (size_t)(v * BATCH + b) * DIM + d);
            float2 a0 = __bfloat1622float2(*reinterpret_cast<const __nv_bfloat162*>(&u.x));
            float2 a1 = __bfloat1622float2(*reinterpret_cast<const __nv_bfloat162*>(&u.y));
            acc.x += a0.x; acc.y += a0.y; acc.z += a1.x; acc.w += a1.y;
        }
    }
    *reinterpret_cast<float4*>(g_Ssum + cls * DIM + d) = acc;
}

// ------------------------- kernel 4: fp8 GEMM on upper triangle, f16x2 exp epilogue -------------------------
__global__ void __launch_bounds__(1024, 1) supcon_main() {
    extern __shared__ char smem[];
    const int t = threadIdx.x, lane = t & 31, wid = t >> 5;
    const int warp_m = wid >> 2, warp_n = wid & 3;      // 8 x 4 warps, 16x32 tiles
    const int iblk = blockIdx.x;                         // row block 0..63
    const int sseg = blockIdx.y;                         // c-range segment 0..1
    const int row_base = iblk * 128;
    const int cbase = sseg ? 17 : 0;
    const int cend  = sseg ? ((iblk < 32) ? 33 : 32) : 17;   // exclusive
    const int NCHUNK = 2 * (cend - cbase);
    const uint32_t sbase = smem_u32(smem);

    // full-K A tile (128 rows x 512 fp8)
    for (int f = t; f < 4096; f += 1024) {
        int row = f >> 5, seg = f & 31;
        uint4 v = *reinterpret_cast<const uint4*>(g_A8 + (size_t)(row_base + row) * DIM + seg * 16);
        *reinterpret_cast<uint4*>(smem + OFF_A + row * A_STRIDE + seg * 16) = v;
    }

    // hoisted prefetch offsets (2 cp16 per thread per chunk)
    const uint32_t so0 = OFF_B + (t >> 4) * B_STRIDE + (t & 15) * 16;
    const uint32_t so1 = OFF_B + ((t + 1024) >> 4) * B_STRIDE + (t & 15) * 16;
    const uint32_t go0 = (uint32_t)(t >> 4) * DIM + (t & 15) * 16;
    const uint32_t go1 = (uint32_t)((t + 1024) >> 4) * DIM + (t & 15) * 16;

    const uint32_t abase = sbase + OFF_A + (warp_m * 16 + (lane & 15)) * A_STRIDE + (lane >> 4) * 16;
    const uint32_t bbase0 = sbase + OFF_B +
        (((lane & 7) + ((lane >> 4) & 1) * 8) + warp_n * 32) * B_STRIDE + ((lane >> 3) & 1) * 16;

    float acc[4][4];
#pragma unroll
    for (int n = 0; n < 4; n++)
#pragma unroll
        for (int r = 0; r < 4; r++) acc[n][r] = 0.f;
    float z0 = 0.f, z1 = 0.f;      // row exp-sums (biased by 2^-EBIAS), rows h=0,1

    {   // prefetch chunks 0,1
        const int jb0 = (iblk + cbase) & 63;
        const uint8_t* gb = g_A8 + (size_t)jb0 * (128 * DIM);
        cp16(sbase + so0, gb + go0); cp16(sbase + so1, gb + go1); cp_commit();
        cp16(sbase + B_STAGE + so0, gb + 256 + go0); cp16(sbase + B_STAGE + so1, gb + 256 + go1); cp_commit();
    }

    for (int c = 0; c < NCHUNK; c++) {
        if (c < NCHUNK - 2) cp_wait<1>(); else cp_wait<0>();
        __syncthreads();
        if (c + 2 < NCHUNK) {
            const int cc = c + 2;
            const int jb = (iblk + cbase + (cc >> 1)) & 63;
            const uint8_t* gb = g_A8 + (size_t)jb * (128 * DIM) + (cc & 1) * 256;
            const uint32_t bo = (cc % 3) * B_STAGE;
            cp16(sbase + bo + so0, gb + go0);
            cp16(sbase + bo + so1, gb + go1);
            cp_commit();
        }

        const uint32_t bb = bbase0 + (c % 3) * B_STAGE;
        const int ch = c & 1;
#pragma unroll
        for (int ks = 0; ks < 8; ks++) {
            const int koff = (ch * 8 + ks) * 32;
            uint32_t a[4];
            ldm4(a, abase + koff);
            uint32_t b[4][2];
#pragma unroll
            for (int p = 0; p < 2; p++) {
                uint32_t r4[4];
                ldm4(r4, bb + p * (16 * B_STRIDE) + ks * 32);
                b[2 * p][0] = r4[0]; b[2 * p][1] = r4[1];
                b[2 * p + 1][0] = r4[2]; b[2 * p + 1][1] = r4[3];
            }
#pragma unroll
            for (int n = 0; n < 4; n++) qmma(acc[n], a, b[n]);
        }

        if (ch) {                              // tile complete -> f16x2 epilogue
            const int ctile = cbase + (c >> 1);
            const int jblk = (iblk + ctile) & 63;
            const bool dg = (ctile == 0);
            uint32_t zh0 = 0, zh1 = 0;
            uint32_t csh[4] = {0, 0, 0, 0};
#pragma unroll
            for (int n = 0; n < 4; n++)
#pragma unroll
                for (int h = 0; h < 2; h++) {
                    float x0 = acc[n][2 * h]     * C_EXP - EBIAS;
                    float x1 = acc[n][2 * h + 1] * C_EXP - EBIAS;
                    if (dg) {
                        int rl = warp_m * 16 + h * 8 + (lane >> 2);
                        int cl0 = warp_n * 32 + n * 8 + (lane & 3) * 2;
                        if (rl == cl0)     x0 = -60.f;
                        if (rl == cl0 + 1) x1 = -60.f;
                    }
                    uint32_t e2 = ex2_h2(pack_h2(x0, x1));
                    if (h == 0) zh0 = hadd2(zh0, e2); else zh1 = hadd2(zh1, e2);
                    csh[n] = hadd2(csh[n], e2);
                    acc[n][2 * h] = 0.f; acc[n][2 * h + 1] = 0.f;
                }
            float2 f0 = h2_to_f2(zh0), f1 = h2_to_f2(zh1);
            z0 += f0.x + f0.y;
            z1 += f1.x + f1.y;
            if (!dg) {
#pragma unroll
                for (int n = 0; n < 4; n++) {
                    uint32_t v = csh[n];
                    v = hadd2(v, __shfl_xor_sync(0xffffffffu, v, 4));
                    v = hadd2(v, __shfl_xor_sync(0xffffffffu, v, 8));
                    v = hadd2(v, __shfl_xor_sync(0xffffffffu, v, 16));
                    csh[n] = v;
                }
                if (lane < 4) {
                    float* zj = &g_Z[jblk * 128 + warp_n * 32 + lane * 2];
#pragma unroll
                    for (int n = 0; n < 4; n++) {
                        float2 f = h2_to_f2(csh[n]);
                        atomicAdd(&zj[n * 8 + 0], f.x * ESCALE);
                        atomicAdd(&zj[n * 8 + 1], f.y * ESCALE);
                    }
                }
            }
        }
    }

    // row z: reduce over quad lanes, then across warp_n via smem
    z0 += __shfl_xor_sync(0xffffffffu, z0, 1);
    z0 += __shfl_xor_sync(0xffffffffu, z0, 2);
    z1 += __shfl_xor_sync(0xffffffffu, z1, 1);
    z1 += __shfl_xor_sync(0xffffffffu, z1, 2);
    float* red = reinterpret_cast<float*>(smem + OFF_RED);   // [4][128]
    __syncthreads();
    if ((lane & 3) == 0) {
        int g4 = lane >> 2;
        red[warp_n * 128 + warp_m * 16 + g4]     = z0;
        red[warp_n * 128 + warp_m * 16 + 8 + g4] = z1;
    }
    __syncthreads();
    if (t < 128)
        atomicAdd(&g_Z[row_base + t],
                  (red[t] + red[128 + t] + red[256 + t] + red[384 + t]) * ESCALE);
}

// ------------------------- kernel 5: per-row loss (one warp per row) -------------------------
__global__ void finalize1(const int* __restrict__ labels) {
    const int t = threadIdx.x, lane = t & 31, wid = t >> 5;
    const int row = blockIdx.x * 8 + wid;
    const int b = row & (BATCH - 1);
    const int cls = labels[b];
    const uint2* arow = reinterpret_cast<const uint2*>(g_A) + (size_t)row * 128;
    const float4* srow = reinterpret_cast<const float4*>(g_Ssum) + (size_t)cls * 128;
    float dot = 0.f, self = 0.f;
#pragma unroll
    for (int q = 0; q < 4; q++) {
        uint2 u = arow[lane + 32 * q];
        float4 s = srow[lane + 32 * q];
        float2 a0 = __bfloat1622float2(*reinterpret_cast<const __nv_bfloat162*>(&u.x));
        float2 a1 = __bfloat1622float2(*reinterpret_cast<const __nv_bfloat162*>(&u.y));
        dot  += a0.x * s.x + a0.y * s.y + a1.x * s.z + a1.y * s.w;
        self += a0.x * a0.x + a0.y * a0.y + a1.x * a1.x + a1.y * a1.y;
    }
#pragma unroll
    for (int o = 16; o; o >>= 1) {
        dot  += __shfl_xor_sync(0xffffffffu, dot, o);
        self += __shfl_xor_sync(0xffffffffu, self, o);
    }
    if (lane == 0) {
        float C = 2.0f * (float)g_cnt[cls] - 1.0f;
        float Z = g_Z[row];
        float S = (dot - self) * INV_T;
        g_loss[row] = (S - C * logf(Z + 1e-8f)) / (C + 1e-8f);
    }
}

// ------------------------- kernel 6: final mean -------------------------
__global__ void finalize2(float* __restrict__ out) {
    __shared__ float sr[256];
    int t = threadIdx.x;
    float a = 0.f;
    for (int r = t; r < NTOT; r += 256) a += g_loss[r];
    sr[t] = a;
    __syncthreads();
    for (int o = 128; o; o >>= 1) {
        if (t < o) sr[t] += sr[t + o];
        __syncthreads();
    }
    if (t == 0) out[0] = -sr[0] / (float)NTOT;
}

// ------------------------- launch -------------------------
extern "C" void kernel_launch(void* const* d_in, const int* in_sizes, int n_in,
                              void* d_out, int out_size) {
    const float* feats = (const float*)d_in[0];
    const int* labels = (const int*)d_in[1];
    (void)in_sizes; (void)n_in; (void)out_size;

    cudaFuncSetAttribute(supcon_main, cudaFuncAttributeMaxDynamicSharedMemorySize, SMEM_TOTAL);

    norm_kernel<<<NTOT / 8, 256>>>(feats);
    hist_kernel<<<1, 1024>>>(labels);
    class_sum<<<NCLS, 128>>>(labels);
    supcon_main<<<dim3(64, 2), 1024, SMEM_TOTAL>>>();
    finalize1<<<NTOT / 8, 256>>>(labels);
    finalize2<<<1, 256>>>((float*)d_out);
}

// round 7
// speedup vs baseline: 1.8129x; 1.0855x over previous
#include <cuda_runtime.h>
#include <cuda_bf16.h>
#include <cuda_fp8.h>
#include <cstdint>

#define BATCH 4096
#define NVIEW 2
#define DIM   512
#define NTOT  8192
#define NCLS  1000

#define C_EXP  20.60992915555662f   // log2(e)/0.07
#define INV_T  14.285714285714286f  // 1/0.07
#define EBIAS  10.0f
#define ESCALE 1024.0f              // 2^EBIAS

// ---------------- smem layout (bytes) ----------------
#define A_STRIDE   528                 // 512 fp8 + 16 pad per row (16*33 -> conflict-free ldmatrix)
#define TILE_BYTES (128 * A_STRIDE)    // 67584
#define OFF_A      0
#define OFF_B      TILE_BYTES          // two full-K B stages
#define OFF_RED    (OFF_B + 2 * TILE_BYTES)   // 202752
#define OFF_MBAR   (OFF_RED + 4 * 128 * 4)    // 204800
#define SMEM_TOTAL (OFF_MBAR + 16)            // 204816

// ---------------- scratch ----------------
__device__ __align__(16) __nv_bfloat16 g_A[(size_t)NTOT * DIM];
__device__ __align__(16) uint8_t       g_A8[(size_t)NTOT * DIM];
__device__ __align__(16) float         g_Ssum[NCLS * DIM];
__device__ float g_Z[NTOT];
__device__ float g_loss[NTOT];
__device__ int   g_cnt[NCLS];

// ---------------- PTX helpers ----------------
__device__ __forceinline__ void ldm4(uint32_t r[4], uint32_t addr) {
    asm volatile("ldmatrix.sync.aligned.m8n8.x4.shared.b16 {%0,%1,%2,%3}, [%4];"
        : "=r"(r[0]), "=r"(r[1]), "=r"(r[2]), "=r"(r[3]) : "r"(addr));
}
__device__ __forceinline__ void qmma(float c[4], const uint32_t a[4], const uint32_t b[2]) {
    asm volatile("mma.sync.aligned.m16n8k32.row.col.f32.e4m3.e4m3.f32 "
        "{%0,%1,%2,%3}, {%4,%5,%6,%7}, {%8,%9}, {%0,%1,%2,%3};"
        : "+f"(c[0]), "+f"(c[1]), "+f"(c[2]), "+f"(c[3])
        : "r"(a[0]), "r"(a[1]), "r"(a[2]), "r"(a[3]), "r"(b[0]), "r"(b[1]));
}
__device__ __forceinline__ uint32_t smem_u32(const void* p) {
    uint32_t a;
    asm("{ .reg .u64 t; cvta.to.shared.u64 t, %1; cvt.u32.u64 %0, t; }" : "=r"(a) : "l"(p));
    return a;
}
__device__ __forceinline__ void bulk_cp(uint32_t dst, const void* src, uint32_t bytes, uint32_t mbar) {
    asm volatile("cp.async.bulk.shared::cta.global.mbarrier::complete_tx::bytes [%0], [%1], %2, [%3];"
        :: "r"(dst), "l"(src), "r"(bytes), "r"(mbar) : "memory");
}
__device__ __forceinline__ void mbar_init(uint32_t mbar, uint32_t cnt) {
    asm volatile("mbarrier.init.shared.b64 [%0], %1;" :: "r"(mbar), "r"(cnt) : "memory");
}
__device__ __forceinline__ void mbar_expect(uint32_t mbar, uint32_t bytes) {
    asm volatile("mbarrier.arrive.expect_tx.shared.b64 _, [%0], %1;" :: "r"(mbar), "r"(bytes) : "memory");
}
__device__ __forceinline__ void mbar_wait(uint32_t mbar, uint32_t parity) {
    uint32_t done;
    asm volatile("{ .reg .pred p; mbarrier.try_wait.parity.acquire.cta.shared::cta.b64 p, [%1], %2; selp.b32 %0, 1, 0, p; }"
        : "=r"(done) : "r"(mbar), "r"(parity) : "memory");
    if (!done) {
        asm volatile("{ .reg .pred P1;\n"
            "W_%=: mbarrier.try_wait.parity.acquire.cta.shared::cta.b64 P1, [%0], %1, 0x989680;\n"
            "@P1 bra.uni D_%=;\n bra.uni W_%=;\n D_%=: }"
            :: "r"(mbar), "r"(parity) : "memory");
    }
}
__device__ __forceinline__ uint32_t pack_h2(float lo, float hi) {
    uint32_t h;
    asm("cvt.rn.f16x2.f32 %0, %1, %2;" : "=r"(h) : "f"(hi), "f"(lo));
    return h;
}
__device__ __forceinline__ uint32_t ex2_h2(uint32_t x) {
    uint32_t e;
    asm("ex2.approx.f16x2 %0, %1;" : "=r"(e) : "r"(x));
    return e;
}
__device__ __forceinline__ uint32_t hadd2(uint32_t a, uint32_t b) {
    uint32_t d;
    asm("add.rn.f16x2 %0, %1, %2;" : "=r"(d) : "r"(a), "r"(b));
    return d;
}
__device__ __forceinline__ float2 h2_to_f2(uint32_t h) {
    float lo, hi;
    asm("{ .reg .f16 l, hh; mov.b32 {l, hh}, %2; cvt.f32.f16 %0, l; cvt.f32.f16 %1, hh; }"
        : "=f"(lo), "=f"(hi) : "r"(h));
    return make_float2(lo, hi);
}

// ------------------------- kernel 1: normalize + view-swap -> bf16 + fp8 (+zero g_Z) -------------------------
__global__ void norm_kernel(const float* __restrict__ feats) {
    int warp = threadIdx.x >> 5, lane = threadIdx.x & 31;
    int row  = blockIdx.x * 8 + warp;
    int b = row & (BATCH - 1);
    int v = row >> 12;
    const float4* src = reinterpret_cast<const float4*>(feats + (size_t)(b * NVIEW + v) * DIM);
    float4 f[4];
    float ss = 0.f;
#pragma unroll
    for (int q = 0; q < 4; q++) {
        f[q] = src[lane + 32 * q];
        ss += f[q].x * f[q].x + f[q].y * f[q].y + f[q].z * f[q].z + f[q].w * f[q].w;
    }
#pragma unroll
    for (int o = 16; o; o >>= 1) ss += __shfl_xor_sync(0xffffffffu, ss, o);
    float sc = 1.0f / fmaxf(sqrtf(ss), 1e-8f);
    if (lane == 0) g_Z[row] = 0.f;
    uint2* dst = reinterpret_cast<uint2*>(g_A + (size_t)row * DIM);
    uint32_t* dst8 = reinterpret_cast<uint32_t*>(g_A8 + (size_t)row * DIM);
#pragma unroll
    for (int q = 0; q < 4; q++) {
        float x = f[q].x * sc, y = f[q].y * sc, z = f[q].z * sc, w = f[q].w * sc;
        __nv_bfloat162 p0 = __floats2bfloat162_rn(x, y);
        __nv_bfloat162 p1 = __floats2bfloat162_rn(z, w);
        uint2 pk;
        pk.x = *reinterpret_cast<uint32_t*>(&p0);
        pk.y = *reinterpret_cast<uint32_t*>(&p1);
        dst[lane + 32 * q] = pk;
        __nv_fp8x2_storage_t lo = __nv_cvt_float2_to_fp8x2(make_float2(x, y), __NV_SATFINITE, __NV_E4M3);
        __nv_fp8x2_storage_t hi = __nv_cvt_float2_to_fp8x2(make_float2(z, w), __NV_SATFINITE, __NV_E4M3);
        dst8[lane + 32 * q] = (uint32_t)lo | ((uint32_t)hi << 16);
    }
}

// ------------------------- kernel 2: per-class feature sums + counts (deterministic) -------------------------
__global__ void class_sum(const int* __restrict__ labels) {
    const int cls = blockIdx.x;
    const int t = threadIdx.x, lane = t & 31;
    __shared__ int list[160];
    __shared__ int ncnt;
    if (t < 32) {
        int n = 0;
        for (int base = 0; base < BATCH; base += 32) {
            int lb = labels[base + lane];
            unsigned bal = __ballot_sync(0xffffffffu, lb == cls);
            if (lb == cls) {
                int pos = n + __popc(bal & ((1u << lane) - 1));
                if (pos < 160) list[pos] = base + lane;
            }
            n += __popc(bal);
        }
        if (lane == 0) { g_cnt[cls] = n; ncnt = (n < 160) ? n : 160; }
    }
    __syncthreads();
    const int n = ncnt;
    const int d = t * 4;
    float4 acc = make_float4(0.f, 0.f, 0.f, 0.f);
    for (int k = 0; k < n; k++) {
        int b = list[k];
#pragma unroll
        for (int v = 0; v < 2; v++) {
            const uint2 u = *reinterpret_cast<const uint2*>(g_A + (size_t)(v * BATCH + b) * DIM + d);
            float2 a0 = __bfloat1622float2(*reinterpret_cast<const __nv_bfloat162*>(&u.x));
            float2 a1 = __bfloat1622float2(*reinterpret_cast<const __nv_bfloat162*>(&u.y));
            acc.x += a0.x; acc.y += a0.y; acc.z += a1.x; acc.w += a1.y;
        }
    }
    *reinterpret_cast<float4*>(g_Ssum + cls * DIM + d) = acc;
}

// ------------------------- kernel 3: fp8 GEMM upper triangle, bulk-copy pipeline -------------------------
__global__ void __launch_bounds__(512, 1) supcon_main() {
    extern __shared__ char smem[];
    const int t = threadIdx.x, lane = t & 31, wid = t >> 5;
    const int warp_m = wid >> 2, warp_n = wid & 3;      // 4 x 4 warps, 32x32 tiles
    const int iblk = blockIdx.x;                         // row block 0..63
    const int sseg = blockIdx.y;                         // c-range segment 0..1
    const int row_base = iblk * 128;
    const int cbase = sseg ? 17 : 0;
    const int cend  = sseg ? ((iblk < 32) ? 33 : 32) : 17;   // exclusive
    const int NTILE = cend - cbase;
    const uint32_t sbase = smem_u32(smem);
    const uint32_t mb = sbase + OFF_MBAR;

    if (t == 0) { mbar_init(mb, 1); mbar_init(mb + 8, 1); }

    // full-K A tile (128 rows x 512 fp8), padded stride
    for (int f = t; f < 4096; f += 512) {
        int row = f >> 5, seg = f & 31;
        uint4 v = *reinterpret_cast<const uint4*>(g_A8 + (size_t)(row_base + row) * DIM + seg * 16);
        *reinterpret_cast<uint4*>(smem + OFF_A + row * A_STRIDE + seg * 16) = v;
    }
    __syncthreads();   // A visible + mbars initialized

    // prologue: bulk-copy tile 0 into buf 0
    {
        const int jb = (iblk + cbase) & 63;
        if (t == 0) mbar_expect(mb, 128 * 512);
        if (t < 128)
            bulk_cp(sbase + OFF_B + t * A_STRIDE, g_A8 + (size_t)jb * (128 * DIM) + t * 512, 512, mb);
    }

    const uint32_t abase = sbase + OFF_A + (warp_m * 32 + (lane & 15)) * A_STRIDE + (lane >> 4) * 16;
    const uint32_t bb_lane = (((lane & 7) + ((lane >> 4) & 1) * 8) + warp_n * 32) * A_STRIDE + ((lane >> 3) & 1) * 16;

    float acc[2][4][4];
#pragma unroll
    for (int m = 0; m < 2; m++)
#pragma unroll
        for (int n = 0; n < 4; n++)
#pragma unroll
            for (int r = 0; r < 4; r++) acc[m][n][r] = 0.f;
    float z[4] = {0.f, 0.f, 0.f, 0.f};

    for (int j = 0; j < NTILE; j++) {
        const int buf = j & 1;
        __syncthreads();                 // all warps done with buf^1 (tile j-1)
        if (j + 1 < NTILE) {
            const int jb = (iblk + cbase + j + 1) & 63;
            const uint32_t mbn = mb + 8 * (buf ^ 1);
            if (t == 0) mbar_expect(mbn, 128 * 512);
            if (t < 128)
                bulk_cp(sbase + OFF_B + (buf ^ 1) * TILE_BYTES + t * A_STRIDE,
                        g_A8 + (size_t)jb * (128 * DIM) + t * 512, 512, mbn);
        }
        mbar_wait(mb + 8 * buf, (j >> 1) & 1);

        const uint32_t bb = sbase + OFF_B + buf * TILE_BYTES + bb_lane;
#pragma unroll
        for (int ks = 0; ks < 16; ks++) {
            const int koff = ks * 32;
            uint32_t a[2][4];
            ldm4(a[0], abase + koff);
            ldm4(a[1], abase + 16 * A_STRIDE + koff);
            uint32_t b[4][2];
#pragma unroll
            for (int p = 0; p < 2; p++) {
                uint32_t r4[4];
                ldm4(r4, bb + p * (16 * A_STRIDE) + koff);
                b[2 * p][0] = r4[0]; b[2 * p][1] = r4[1];
                b[2 * p + 1][0] = r4[2]; b[2 * p + 1][1] = r4[3];
            }
#pragma unroll
            for (int m = 0; m < 2; m++)
#pragma unroll
                for (int n = 0; n < 4; n++) qmma(acc[m][n], a[m], b[n]);
        }

        // ---- epilogue: f16x2 exp, row sums + REDG column sums ----
        {
            const int ctile = cbase + j;
            const int jblk = (iblk + ctile) & 63;
            const bool dg = (ctile == 0);
            uint32_t zh[4] = {0, 0, 0, 0};
            uint32_t csh[4] = {0, 0, 0, 0};
#pragma unroll
            for (int m = 0; m < 2; m++)
#pragma unroll
                for (int n = 0; n < 4; n++)
#pragma unroll
                    for (int h = 0; h < 2; h++) {
                        float x0 = acc[m][n][2 * h]     * C_EXP - EBIAS;
                        float x1 = acc[m][n][2 * h + 1] * C_EXP - EBIAS;
                        if (dg) {
                            int rl = warp_m * 32 + m * 16 + h * 8 + (lane >> 2);
                            int cl0 = warp_n * 32 + n * 8 + (lane & 3) * 2;
                            if (rl == cl0)     x0 = -60.f;
                            if (rl == cl0 + 1) x1 = -60.f;
                        }
                        uint32_t e2 = ex2_h2(pack_h2(x0, x1));
                        zh[2 * m + h] = hadd2(zh[2 * m + h], e2);
                        csh[n] = hadd2(csh[n], e2);
                        acc[m][n][2 * h] = 0.f; acc[m][n][2 * h + 1] = 0.f;
                    }
#pragma unroll
            for (int g = 0; g < 4; g++) {
                float2 f = h2_to_f2(zh[g]);
                z[g] += f.x + f.y;
            }
            if (!dg) {
#pragma unroll
                for (int n = 0; n < 4; n++) {
                    uint32_t v = csh[n];
                    v = hadd2(v, __shfl_xor_sync(0xffffffffu, v, 4));
                    v = hadd2(v, __shfl_xor_sync(0xffffffffu, v, 8));
                    v = hadd2(v, __shfl_xor_sync(0xffffffffu, v, 16));
                    csh[n] = v;
                }
                if (lane < 4) {
                    float* zj = &g_Z[jblk * 128 + warp_n * 32 + lane * 2];
#pragma unroll
                    for (int n = 0; n < 4; n++) {
                        float2 f = h2_to_f2(csh[n]);
                        atomicAdd(&zj[n * 8 + 0], f.x * ESCALE);
                        atomicAdd(&zj[n * 8 + 1], f.y * ESCALE);
                    }
                }
            }
        }
    }

    // row z: reduce over quad lanes, then across warp_n via smem
#pragma unroll
    for (int g = 0; g < 4; g++) {
        z[g] += __shfl_xor_sync(0xffffffffu, z[g], 1);
        z[g] += __shfl_xor_sync(0xffffffffu, z[g], 2);
    }
    float* red = reinterpret_cast<float*>(smem + OFF_RED);   // [4][128]
    __syncthreads();
    if ((lane & 3) == 0) {
        int g4 = lane >> 2;
#pragma unroll
        for (int m = 0; m < 2; m++)
#pragma unroll
            for (int h = 0; h < 2; h++) {
                int rl = warp_m * 32 + m * 16 + h * 8 + g4;
                red[warp_n * 128 + rl] = z[2 * m + h];
            }
    }
    __syncthreads();
    if (t < 128)
        atomicAdd(&g_Z[row_base + t],
                  (red[t] + red[128 + t] + red[256 + t] + red[384 + t]) * ESCALE);
}

// ------------------------- kernel 4: per-row loss (one warp per row) -------------------------
__global__ void finalize1(const int* __restrict__ labels) {
    const int t = threadIdx.x, lane = t & 31, wid = t >> 5;
    const int row = blockIdx.x * 8 + wid;
    const int b = row & (BATCH - 1);
    const int cls = labels[b];
    const uint2* arow = reinterpret_cast<const uint2*>(g_A) + (size_t)row * 128;
    const float4* srow = reinterpret_cast<const float4*>(g_Ssum) + (size_t)cls * 128;
    float dot = 0.f, self = 0.f;
#pragma unroll
    for (int q = 0; q < 4; q++) {
        uint2 u = arow[lane + 32 * q];
        float4 s = srow[lane + 32 * q];
        float2 a0 = __bfloat1622float2(*reinterpret_cast<const __nv_bfloat162*>(&u.x));
        float2 a1 = __bfloat1622float2(*reinterpret_cast<const __nv_bfloat162*>(&u.y));
        dot  += a0.x * s.x + a0.y * s.y + a1.x * s.z + a1.y * s.w;
        self += a0.x * a0.x + a0.y * a0.y + a1.x * a1.x + a1.y * a1.y;
    }
#pragma unroll
    for (int o = 16; o; o >>= 1) {
        dot  += __shfl_xor_sync(0xffffffffu, dot, o);
        self += __shfl_xor_sync(0xffffffffu, self, o);
    }
    if (lane == 0) {
        float C = 2.0f * (float)g_cnt[cls] - 1.0f;
        float Z = g_Z[row];
        float S = (dot - self) * INV_T;
        g_loss[row] = (S - C * logf(Z + 1e-8f)) / (C + 1e-8f);
    }
}

// ------------------------- kernel 5: final mean -------------------------
__global__ void finalize2(float* __restrict__ out) {
    __shared__ float sr[256];
    int t = threadIdx.x;
    float a = 0.f;
    for (int r = t; r < NTOT; r += 256) a += g_loss[r];
    sr[t] = a;
    __syncthreads();
    for (int o = 128; o; o >>= 1) {
        if (t < o) sr[t] += sr[t + o];
        __syncthreads();
    }
    if (t == 0) out[0] = -sr[0] / (float)NTOT;
}

// ------------------------- launch -------------------------
extern "C" void kernel_launch(void* const* d_in, const int* in_sizes, int n_in,
                              void* d_out, int out_size) {
    const float* feats = (const float*)d_in[0];
    const int* labels = (const int*)d_in[1];
    (void)in_sizes; (void)n_in; (void)out_size;

    cudaFuncSetAttribute(supcon_main, cudaFuncAttributeMaxDynamicSharedMemorySize, SMEM_TOTAL);

    norm_kernel<<<NTOT / 8, 256>>>(feats);
    class_sum<<<NCLS, 128>>>(labels);
    supcon_main<<<dim3(64, 2), 512, SMEM_TOTAL>>>();
    finalize1<<<NTOT / 8, 256>>>(labels);
    finalize2<<<1, 256>>>((float*)d_out);
}